// round 6
// baseline (speedup 1.0000x reference)
#include <cuda_runtime.h>
#include <cstdint>

// 3D Haar DWT, level 1, x [B=2, C=32, D=64, H=128, W=128] f32
// -> out [B, 8C, D/2, H/2, W/2], subband order aaa,aad,ada,add,daa,dad,dda,ddd
// (bits: depth,height,width; channel = sb*C + c).
//
// R5: 256-bit global accesses (sm_100a+ LDG.E.256 / STG.E.256).
// 8 output-w per thread: 8x ld.global.nc.v8 in, 8x st.global.cs.v8 out.
// Per-warp per-subband store burst = 1KB contiguous. HBM-bound, 512MB stream.

#define B_   2
#define C_   32
#define D_   64
#define H_   128
#define W_   128
#define DH   (D_/2)
#define HH   (H_/2)
#define WH   (W_/2)
#define WT   (WH/8)   // 8 = output-w positions per thread -> WT=8 thread slots along W

__device__ __forceinline__ void ldg_v8(const float* p, float* v) {
    uint32_t a,b,c,d,e,f,g,h;
    asm volatile("ld.global.nc.v8.b32 {%0,%1,%2,%3,%4,%5,%6,%7}, [%8];"
        : "=r"(a),"=r"(b),"=r"(c),"=r"(d),"=r"(e),"=r"(f),"=r"(g),"=r"(h)
        : "l"(p));
    v[0]=__uint_as_float(a); v[1]=__uint_as_float(b);
    v[2]=__uint_as_float(c); v[3]=__uint_as_float(d);
    v[4]=__uint_as_float(e); v[5]=__uint_as_float(f);
    v[6]=__uint_as_float(g); v[7]=__uint_as_float(h);
}

__device__ __forceinline__ void stg_v8_cs(float* p, const float* v) {
    asm volatile("st.global.cs.v8.b32 [%0], {%1,%2,%3,%4,%5,%6,%7,%8};"
        :: "l"(p),
           "r"(__float_as_uint(v[0])), "r"(__float_as_uint(v[1])),
           "r"(__float_as_uint(v[2])), "r"(__float_as_uint(v[3])),
           "r"(__float_as_uint(v[4])), "r"(__float_as_uint(v[5])),
           "r"(__float_as_uint(v[6])), "r"(__float_as_uint(v[7]))
        : "memory");
}

// haar butterfly for one 2x2x2 cube; writes 8 subband values * K.
__device__ __forceinline__ void haar_cube(
    float x000, float x001, float x010, float x011,
    float x100, float x101, float x110, float x111,
    float s[8][8], int k)
{
    const float K = 0.35355339059327373f;  // (1/sqrt2)^3
    float wl0 = x000 + x001, wh0 = x000 - x001;
    float wl1 = x010 + x011, wh1 = x010 - x011;
    float wl2 = x100 + x101, wh2 = x100 - x101;
    float wl3 = x110 + x111, wh3 = x110 - x111;
    float hl_l0 = wl0 + wl1, hh_l0 = wl0 - wl1;
    float hl_h0 = wh0 + wh1, hh_h0 = wh0 - wh1;
    float hl_l1 = wl2 + wl3, hh_l1 = wl2 - wl3;
    float hl_h1 = wh2 + wh3, hh_h1 = wh2 - wh3;
    s[0][k] = (hl_l0 + hl_l1) * K;
    s[1][k] = (hl_h0 + hl_h1) * K;
    s[2][k] = (hh_l0 + hh_l1) * K;
    s[3][k] = (hh_h0 + hh_h1) * K;
    s[4][k] = (hl_l0 - hl_l1) * K;
    s[5][k] = (hl_h0 - hl_h1) * K;
    s[6][k] = (hh_l0 - hh_l1) * K;
    s[7][k] = (hh_h0 - hh_h1) * K;
}

__global__ void __launch_bounds__(256) haar3d_kernel(
    const float* __restrict__ x, float* __restrict__ out)
{
    int t = blockIdx.x * blockDim.x + threadIdx.x;
    // t = ((((b*C + c)*DH + dz)*HH + dy)*WT + wq)
    int wq =  t        & (WT - 1);         // 0..7
    int dy = (t >> 3)  & (HH - 1);         // 0..63
    int dz = (t >> 9)  & (DH - 1);         // 0..31
    int c  = (t >> 14) & (C_ - 1);         // 0..31
    int b  =  t >> 19;                     // 0..1

    // ---- input: 16 floats per row (w), 4 rows -> 8x LDG.256 ----
    size_t ibase = ((((size_t)(b * C_ + c) * D_ + 2 * dz) * H_ + 2 * dy) * W_) + 16 * wq;
    const size_t HW = (size_t)H_ * W_;

    float r00[16], r01[16], r10[16], r11[16];
    ldg_v8(x + ibase,               r00);     // d0 h0 lo
    ldg_v8(x + ibase + 8,           r00 + 8); // d0 h0 hi
    ldg_v8(x + ibase + W_,          r01);
    ldg_v8(x + ibase + W_ + 8,      r01 + 8);
    ldg_v8(x + ibase + HW,          r10);
    ldg_v8(x + ibase + HW + 8,      r10 + 8);
    ldg_v8(x + ibase + HW + W_,     r11);
    ldg_v8(x + ibase + HW + W_ + 8, r11 + 8);

    // ---- 8 cubes ----
    float s[8][8];
#pragma unroll
    for (int k = 0; k < 8; k++) {
        haar_cube(r00[2*k], r00[2*k+1], r01[2*k], r01[2*k+1],
                  r10[2*k], r10[2*k+1], r11[2*k], r11[2*k+1], s, k);
    }

    // ---- 8x STG.256 (streaming), one per subband; channel = sb*C + c ----
    size_t obase = ((((size_t)(b * 8 * C_ + c) * DH + dz) * HH + dy) * WH) + 8 * wq;
    const size_t sbStride = (size_t)C_ * DH * HH * WH;

#pragma unroll
    for (int sb = 0; sb < 8; sb++) {
        stg_v8_cs(out + obase + (size_t)sb * sbStride, s[sb]);
    }
}

extern "C" void kernel_launch(void* const* d_in, const int* in_sizes, int n_in,
                              void* d_out, int out_size) {
    const float* x = (const float*)d_in[0];
    float* out = (float*)d_out;
    // total threads = B*C*DH*HH*WT = 2*32*32*64*8 = 1,048,576
    const int total = B_ * C_ * DH * HH * WT;
    haar3d_kernel<<<total / 256, 256>>>(x, out);
}

// round 7
// speedup vs baseline: 1.0078x; 1.0078x over previous
#include <cuda_runtime.h>
#include <cstdint>

// 3D Haar DWT, level 1, x [B=2, C=32, D=64, H=128, W=128] f32
// -> out [B, 8C, D/2, H/2, W/2], subband order aaa,aad,ada,add,daa,dad,dda,ddd
// (bits: depth,height,width; channel = sb*C + c).
//
// R6: revert to R1 granularity (best: occ 75%, DRAM 82%) — 2 cubes/thread,
// 4x LDG.128 in, 8x STG.64 out — plus streaming cache hints (.cs) on both
// sides. Evidence from R2/R5: DRAM% tracks warp concurrency, so keep the
// lightest thread. Pure 512 MB stream, HBM-bound.

#define B_   2
#define C_   32
#define D_   64
#define H_   128
#define W_   128
#define DH   (D_/2)
#define HH   (H_/2)
#define WH   (W_/2)
#define WQ   (W_/4)   // thread handles 2 output-w positions (4 input w)

__device__ __forceinline__ float4 ldg_v4_cs(const float* p) {
    uint32_t a, b, c, d;
    asm volatile("ld.global.cs.v4.b32 {%0,%1,%2,%3}, [%4];"
        : "=r"(a), "=r"(b), "=r"(c), "=r"(d) : "l"(p));
    return make_float4(__uint_as_float(a), __uint_as_float(b),
                       __uint_as_float(c), __uint_as_float(d));
}

__device__ __forceinline__ void stg_v2_cs(float* p, float lo, float hi) {
    asm volatile("st.global.cs.v2.b32 [%0], {%1,%2};"
        :: "l"(p), "r"(__float_as_uint(lo)), "r"(__float_as_uint(hi))
        : "memory");
}

__global__ void __launch_bounds__(256) haar3d_kernel(
    const float* __restrict__ x, float* __restrict__ out)
{
    const float K = 0.35355339059327373f;  // (1/sqrt2)^3

    int t = blockIdx.x * blockDim.x + threadIdx.x;
    // t = ((((b*C + c)*DH + dz)*HH + dy)*WQ + wq)
    int wq =  t        & (WQ - 1);         // 0..31
    int dy = (t >> 5)  & (HH - 1);         // 0..63
    int dz = (t >> 11) & (DH - 1);         // 0..31
    int c  = (t >> 16) & (C_ - 1);         // 0..31
    int b  =  t >> 21;                     // 0..1

    // ---- input loads: 4 rows x LDG.128 (streaming) ----
    size_t ibase = ((((size_t)(b * C_ + c) * D_ + 2 * dz) * H_ + 2 * dy) * W_) + 4 * wq;
    const size_t HW = (size_t)H_ * W_;
    const float4 r00 = ldg_v4_cs(x + ibase);           // d0 h0
    const float4 r01 = ldg_v4_cs(x + ibase + W_);      // d0 h1
    const float4 r10 = ldg_v4_cs(x + ibase + HW);      // d1 h0
    const float4 r11 = ldg_v4_cs(x + ibase + HW + W_); // d1 h1

    // ---- butterfly: two cubes, p=0 (.x,.y) p=1 (.z,.w) ----
    float wl00a = r00.x + r00.y, wh00a = r00.x - r00.y;
    float wl01a = r01.x + r01.y, wh01a = r01.x - r01.y;
    float wl10a = r10.x + r10.y, wh10a = r10.x - r10.y;
    float wl11a = r11.x + r11.y, wh11a = r11.x - r11.y;

    float wl00b = r00.z + r00.w, wh00b = r00.z - r00.w;
    float wl01b = r01.z + r01.w, wh01b = r01.z - r01.w;
    float wl10b = r10.z + r10.w, wh10b = r10.z - r10.w;
    float wl11b = r11.z + r11.w, wh11b = r11.z - r11.w;

    float s0[8], s1[8];
    {
        float hl_l0 = wl00a + wl01a, hh_l0 = wl00a - wl01a;
        float hl_h0 = wh00a + wh01a, hh_h0 = wh00a - wh01a;
        float hl_l1 = wl10a + wl11a, hh_l1 = wl10a - wl11a;
        float hl_h1 = wh10a + wh11a, hh_h1 = wh10a - wh11a;
        s0[0] = (hl_l0 + hl_l1) * K;
        s0[1] = (hl_h0 + hl_h1) * K;
        s0[2] = (hh_l0 + hh_l1) * K;
        s0[3] = (hh_h0 + hh_h1) * K;
        s0[4] = (hl_l0 - hl_l1) * K;
        s0[5] = (hl_h0 - hl_h1) * K;
        s0[6] = (hh_l0 - hh_l1) * K;
        s0[7] = (hh_h0 - hh_h1) * K;
    }
    {
        float hl_l0 = wl00b + wl01b, hh_l0 = wl00b - wl01b;
        float hl_h0 = wh00b + wh01b, hh_h0 = wh00b - wh01b;
        float hl_l1 = wl10b + wl11b, hh_l1 = wl10b - wl11b;
        float hl_h1 = wh10b + wh11b, hh_h1 = wh10b - wh11b;
        s1[0] = (hl_l0 + hl_l1) * K;
        s1[1] = (hl_h0 + hl_h1) * K;
        s1[2] = (hh_l0 + hh_l1) * K;
        s1[3] = (hh_h0 + hh_h1) * K;
        s1[4] = (hl_l0 - hl_l1) * K;
        s1[5] = (hl_h0 - hl_h1) * K;
        s1[6] = (hh_l0 - hh_l1) * K;
        s1[7] = (hh_h0 - hh_h1) * K;
    }

    // ---- output: 8x STG.64 streaming, one per subband; channel = sb*C + c ----
    size_t obase = ((((size_t)(b * 8 * C_ + c) * DH + dz) * HH + dy) * WH) + 2 * wq;
    const size_t sbStride = (size_t)C_ * DH * HH * WH;

#pragma unroll
    for (int sb = 0; sb < 8; sb++) {
        stg_v2_cs(out + obase + (size_t)sb * sbStride, s0[sb], s1[sb]);
    }
}

extern "C" void kernel_launch(void* const* d_in, const int* in_sizes, int n_in,
                              void* d_out, int out_size) {
    const float* x = (const float*)d_in[0];
    float* out = (float*)d_out;
    // total threads = B*C*DH*HH*WQ = 2*32*32*64*32 = 4,194,304
    const int total = B_ * C_ * DH * HH * WQ;
    haar3d_kernel<<<total / 256, 256>>>(x, out);
}

// round 8
// speedup vs baseline: 1.0082x; 1.0004x over previous
#include <cuda_runtime.h>
#include <cstdint>

// 3D Haar DWT, level 1, x [B=2, C=32, D=64, H=128, W=128] f32
// -> out [B, 8C, D/2, H/2, W/2], subband order aaa,aad,ada,add,daa,dad,dda,ddd
// (bits: depth,height,width; channel = sb*C + c).
//
// R7: smem-staged subband-segregated stores. Compute phase identical to R1
// (2 cubes/thread, 4x LDG.128). Results staged in 16KB smem [sb][dy_l][w];
// drain phase: warp w writes subband w as ONE 2KB contiguous run (4x STG.128
// to consecutive addresses). Tests the write-stream-interleaving hypothesis
// for the 20% gap to HBM spec.

#define B_   2
#define C_   32
#define D_   64
#define H_   128
#define W_   128
#define DH   (D_/2)
#define HH   (H_/2)
#define WH   (W_/2)

__global__ void __launch_bounds__(256) haar3d_kernel(
    const float* __restrict__ x, float* __restrict__ out)
{
    __shared__ float sm[8][8][64];   // [subband][dy_local][w] = 16 KB

    const float K = 0.35355339059327373f;  // (1/sqrt2)^3

    int tid  = threadIdx.x;
    int wq   = tid & 31;        // 0..31 : w-pair index (2 output w per thread)
    int dy_l = tid >> 5;        // 0..7  : local dy row

    // cta = (((b*C + c)*DH + dz)*8 + dyb)
    int cta = blockIdx.x;
    int dyb =  cta        & 7;          // 0..7 (dy block of 8 rows)
    int dz  = (cta >> 3)  & (DH - 1);   // 0..31
    int c   = (cta >> 8)  & (C_ - 1);   // 0..31
    int b   =  cta >> 13;               // 0..1

    int dy = dyb * 8 + dy_l;            // 0..63

    // ---- phase 1: load 4x float4, butterfly (identical to R1) ----
    size_t ibase = ((((size_t)(b * C_ + c) * D_ + 2 * dz) * H_ + 2 * dy) * W_) + 4 * wq;
    const size_t HW = (size_t)H_ * W_;
    const float4 r00 = *(const float4*)(x + ibase);            // d0 h0
    const float4 r01 = *(const float4*)(x + ibase + W_);       // d0 h1
    const float4 r10 = *(const float4*)(x + ibase + HW);       // d1 h0
    const float4 r11 = *(const float4*)(x + ibase + HW + W_);  // d1 h1

    float wl00a = r00.x + r00.y, wh00a = r00.x - r00.y;
    float wl01a = r01.x + r01.y, wh01a = r01.x - r01.y;
    float wl10a = r10.x + r10.y, wh10a = r10.x - r10.y;
    float wl11a = r11.x + r11.y, wh11a = r11.x - r11.y;

    float wl00b = r00.z + r00.w, wh00b = r00.z - r00.w;
    float wl01b = r01.z + r01.w, wh01b = r01.z - r01.w;
    float wl10b = r10.z + r10.w, wh10b = r10.z - r10.w;
    float wl11b = r11.z + r11.w, wh11b = r11.z - r11.w;

    float s0[8], s1[8];
    {
        float hl_l0 = wl00a + wl01a, hh_l0 = wl00a - wl01a;
        float hl_h0 = wh00a + wh01a, hh_h0 = wh00a - wh01a;
        float hl_l1 = wl10a + wl11a, hh_l1 = wl10a - wl11a;
        float hl_h1 = wh10a + wh11a, hh_h1 = wh10a - wh11a;
        s0[0] = (hl_l0 + hl_l1) * K;
        s0[1] = (hl_h0 + hl_h1) * K;
        s0[2] = (hh_l0 + hh_l1) * K;
        s0[3] = (hh_h0 + hh_h1) * K;
        s0[4] = (hl_l0 - hl_l1) * K;
        s0[5] = (hl_h0 - hl_h1) * K;
        s0[6] = (hh_l0 - hh_l1) * K;
        s0[7] = (hh_h0 - hh_h1) * K;
    }
    {
        float hl_l0 = wl00b + wl01b, hh_l0 = wl00b - wl01b;
        float hl_h0 = wh00b + wh01b, hh_h0 = wh00b - wh01b;
        float hl_l1 = wl10b + wl11b, hh_l1 = wl10b - wl11b;
        float hl_h1 = wh10b + wh11b, hh_h1 = wh10b - wh11b;
        s1[0] = (hl_l0 + hl_l1) * K;
        s1[1] = (hl_h0 + hl_h1) * K;
        s1[2] = (hh_l0 + hh_l1) * K;
        s1[3] = (hh_h0 + hh_h1) * K;
        s1[4] = (hl_l0 - hl_l1) * K;
        s1[5] = (hl_h0 - hl_h1) * K;
        s1[6] = (hh_l0 - hh_l1) * K;
        s1[7] = (hh_h0 - hh_h1) * K;
    }

    // ---- stage to smem: STS.64 per subband, conflict-free ----
#pragma unroll
    for (int sb = 0; sb < 8; sb++) {
        *(float2*)&sm[sb][dy_l][2 * wq] = make_float2(s0[sb], s1[sb]);
    }
    __syncthreads();

    // ---- phase 2: warp `wid` drains subband `wid` as one 2KB contiguous run ----
    int wid = tid >> 5;   // 0..7 = subband
    int lid = tid & 31;
    // out channel = wid*C + c ; rows dyb*8 .. dyb*8+7 are contiguous (8*64 floats)
    size_t obase = ((((size_t)(b * 8 * C_ + wid * C_ + c) * DH + dz) * HH + dyb * 8) * WH);
    const float4* src = (const float4*)&sm[wid][0][0];  // 128 float4
    float4* dst = (float4*)(out + obase);
#pragma unroll
    for (int i = 0; i < 4; i++) {
        dst[i * 32 + lid] = src[i * 32 + lid];
    }
}

extern "C" void kernel_launch(void* const* d_in, const int* in_sizes, int n_in,
                              void* d_out, int out_size) {
    const float* x = (const float*)d_in[0];
    float* out = (float*)d_out;
    // grid = B*C*DH*(HH/8) = 2*32*32*8 = 16384 CTAs, 256 threads each
    haar3d_kernel<<<B_ * C_ * DH * (HH / 8), 256>>>(x, out);
}